// round 2
// baseline (speedup 1.0000x reference)
#include <cuda_runtime.h>

#define N_ROWS 512
#define D_COLS 256
#define EPS 1e-7f
#define NBLK 64
#define ROWS_PER_BLK (N_ROWS / NBLK)   // 8

// Column accumulators. Zero at module load; K2 resets them after consuming,
// so every graph replay sees zeros. No device allocation anywhere.
__device__ float gS1[D_COLS];
__device__ float gS2[D_COLS];
__device__ float gA[D_COLS];
__device__ float gB[D_COLS];
__device__ float gC[D_COLS];

// ---------------- K1: streaming column partial sums ----------------
__global__ void __launch_bounds__(D_COLS)
club_pass1(const float* __restrict__ mu,
           const float* __restrict__ logvar,
           const float* __restrict__ h) {
    const int d  = threadIdx.x;                 // column 0..255
    const int r0 = blockIdx.x * ROWS_PER_BLK;

    float s1 = 0.f, s2 = 0.f, a = 0.f, b = 0.f, c = 0.f;

#pragma unroll
    for (int r = 0; r < ROWS_PER_BLK; ++r) {
        const int idx = (r0 + r) * D_COLS + d;  // coalesced row-major
        const float hv = h[idx];
        const float mv = mu[idx];
        const float lv = logvar[idx];
        const float inv = 1.0f / (__expf(lv) + EPS);
        s1 += hv;
        s2 += hv * hv;
        a  += inv * mv;
        b  += inv;
        const float dmh = mv - hv;
        c  += inv * (dmh * dmh - mv * mv);
    }

    // Fire-and-forget reductions (no return value used -> REDG, no fence,
    // no read-back). Kernel boundary orders these before K2.
    atomicAdd(&gS1[d], s1);
    atomicAdd(&gS2[d], s2);
    atomicAdd(&gA[d],  a);
    atomicAdd(&gB[d],  b);
    atomicAdd(&gC[d],  c);
}

// ---------------- K2: combine 256 column totals -> scalar ----------------
__global__ void __launch_bounds__(D_COLS)
club_pass2(float* __restrict__ out) {
    const int d   = threadIdx.x;
    const int lid = d & 31;
    const int wid = d >> 5;

    // Plain loads: K1's atomics are complete and visible at kernel boundary.
    const float S1 = gS1[d];
    const float S2 = gS2[d];
    const float A  = gA[d];
    const float B  = gB[d];
    const float C  = gC[d];

    const float invN = 1.0f / (float)N_ROWS;
    float term = C + 2.0f * (S1 * invN) * A - (S2 * invN) * B;

    // Warp shuffle reduction, then cross-warp via smem.
#pragma unroll
    for (int s = 16; s > 0; s >>= 1)
        term += __shfl_xor_sync(0xFFFFFFFFu, term, s);

    __shared__ float warpsum[8];
    if (lid == 0) warpsum[wid] = term;
    __syncthreads();

    if (d == 0) {
        float tot = 0.f;
#pragma unroll
        for (int w = 0; w < 8; ++w) tot += warpsum[w];
        out[0] = -0.5f * invN * tot;
    }

    // Reset accumulators for the next replay (K2 is the only consumer;
    // the next K1 launch is ordered after this kernel completes).
    gS1[d] = 0.f; gS2[d] = 0.f; gA[d] = 0.f; gB[d] = 0.f; gC[d] = 0.f;
}

extern "C" void kernel_launch(void* const* d_in, const int* in_sizes, int n_in,
                              void* d_out, int out_size) {
    const float* mu     = (const float*)d_in[0];
    const float* logvar = (const float*)d_in[1];
    const float* h      = (const float*)d_in[2];
    float* out          = (float*)d_out;
    club_pass1<<<NBLK, D_COLS>>>(mu, logvar, h);
    club_pass2<<<1, D_COLS>>>(out);
}